// round 5
// baseline (speedup 1.0000x reference)
#include <cuda_runtime.h>
#include <math.h>
#include <float.h>

// ---------------- problem constants ----------------
#define NTOT 32768     // B*NP
#define NB   16
#define NPE  2048      // nodes per event

// ---------------- scratch (device globals; no allocations) ----------------
__device__ __align__(16) float g_x[NTOT * 6];
__device__ __align__(16) float g_s[NTOT * 3];
__device__ __align__(16) float g_h[NTOT * 12];
__device__ __align__(16) float g_agg[NTOT * 24];
__device__ __align__(16) float g_t[NTOT * 6];
__device__ __align__(16) float g_feats[NTOT * 24];
__device__ __align__(16) float g_stats[NB * 18];

// ---------------- helpers ----------------
__device__ __forceinline__ float dot3(float a0, float a1, float a2,
                                      float b0, float b1, float b2) {
    return fmaf(a2, b2, fmaf(a1, b1, a0 * b0));
}
__device__ __forceinline__ float eluf(float x) { return x > 0.f ? x : expm1f(x); }
__device__ __forceinline__ unsigned f2u(float f) {
    unsigned u = __float_as_uint(f);
    return (u & 0x80000000u) ? ~u : (u | 0x80000000u);
}
__device__ __forceinline__ float u2f(unsigned m) {
    unsigned v = (m & 0x80000000u) ? (m ^ 0x80000000u) : ~m;
    return __uint_as_float(v);
}

// ---------------- K0: input embedding + layer-0 s/h projection ----------------
__global__ void k_embed(const float* __restrict__ X, const float* __restrict__ Win,
                        const float* __restrict__ Ws, const float* __restrict__ bs,
                        const float* __restrict__ Wh, const float* __restrict__ bh) {
    int n = blockIdx.x * blockDim.x + threadIdx.x;
    if (n >= NTOT) return;
    float xi[9];
#pragma unroll
    for (int q = 0; q < 9; ++q) xi[q] = X[n * 9 + q];
    float xv[6];
#pragma unroll
    for (int d = 0; d < 6; ++d) {
        float a = 0.f;
#pragma unroll
        for (int q = 0; q < 9; ++q) a = fmaf(xi[q], Win[q * 6 + d], a);
        xv[d] = a;
        g_x[n * 6 + d] = a;
    }
#pragma unroll
    for (int sp = 0; sp < 3; ++sp) {
        float a = bs[sp];
#pragma unroll
        for (int d = 0; d < 6; ++d) a = fmaf(xv[d], Ws[d * 3 + sp], a);
        g_s[n * 3 + sp] = a;
    }
#pragma unroll
    for (int p = 0; p < 12; ++p) {
        float a = bh[p];
#pragma unroll
        for (int d = 0; d < 6; ++d) a = fmaf(xv[d], Wh[d * 12 + p], a);
        g_h[n * 12 + p] = a;
    }
}

// ---------------- K2: GravNet kNN + weighted mean/max aggregation ----------------
#define GR_THREADS 256
#define GR_WARPS   8
#define KMAX       256
#define EQCAP      64
// floats: s4 (2048 float4 = 8192) + hsh (12*2048 = 24576) = 32768
// u32 per warp: d2 2048 + hist 256 + cj KMAX + eq EQCAP
#define GRAV_WORDS (32768u + GR_WARPS * (2048u + 256u + KMAX + EQCAP))
#define GRAV_SMEM_BYTES (GRAV_WORDS * 4u)

__global__ void __launch_bounds__(GR_THREADS, 1) k_grav(int k) {
    extern __shared__ float sm[];
    float4* s4 = (float4*)sm;                // [2048]
    float*  hsh = sm + 8192;                 // [12][2048]
    unsigned* d2all   = (unsigned*)(sm + 32768);
    unsigned* histall = d2all + GR_WARPS * 2048;
    unsigned* cjall   = histall + GR_WARPS * 256;
    unsigned* eqall   = cjall + GR_WARPS * KMAX;

    const int e = blockIdx.y, sub = blockIdx.x;
    const int tid = threadIdx.x, w = tid >> 5, lane = tid & 31;
    const int base = e * NPE;
    const unsigned FULL = 0xffffffffu;
    const unsigned below = (1u << lane) - 1u;

    // stage s (as float4 with |s|^2 in .w)
    for (int i = tid; i < NPE; i += GR_THREADS) {
        float a = g_s[(base + i) * 3 + 0];
        float b = g_s[(base + i) * 3 + 1];
        float c = g_s[(base + i) * 3 + 2];
        s4[i] = make_float4(a, b, c, dot3(a, b, c, a, b, c));
    }
    // stage h transposed to [d][node]
    for (int idx = tid; idx < NPE * 12; idx += GR_THREADS) {
        int i = idx / 12, d = idx - i * 12;
        hsh[d * NPE + i] = g_h[base * 12 + idx];
    }
    // pre-zero cj so no iteration can ever read stale garbage indices
    for (int i = tid; i < (int)(GR_WARPS * KMAX); i += GR_THREADS) cjall[i] = 0u;
    __syncthreads();

    unsigned* d2   = d2all + w * 2048;
    unsigned* hist = histall + w * 256;
    unsigned* cj   = cjall + w * KMAX;
    unsigned* eqs  = eqall + w * EQCAP;
    const float invk = 1.f / (float)k;

    for (int nn = 0; nn < 32; ++nn) {
        const int i = sub * 256 + w * 32 + nn;
        float4 si = s4[i];

        // ---- pass 0: distances + fused top-byte histogram ----
        __syncwarp();
#pragma unroll
        for (int b = 0; b < 8; ++b) hist[lane + 32 * b] = 0u;
        __syncwarp();
        for (int t = 0; t < 64; ++t) {
            int j = (t << 5) | lane;
            float4 sj = s4[j];
            float dd = (si.w + sj.w) - 2.f * dot3(si.x, si.y, si.z, sj.x, sj.y, sj.z);
            unsigned u = f2u(dd);
            d2[j] = u;
            unsigned dig = u >> 24;
            unsigned mk = __match_any_sync(FULL, dig);
            if ((mk & below) == 0u) atomicAdd(&hist[dig], (unsigned)__popc(mk));
        }
        __syncwarp();

        // ---- radix digit picks ----
        unsigned prefix = 0, rk = (unsigned)k;
        for (int pass = 0; pass < 4; ++pass) {
            if (pass > 0) {
                int shift = 24 - 8 * pass;
                __syncwarp();
#pragma unroll
                for (int b = 0; b < 8; ++b) hist[lane + 32 * b] = 0u;
                __syncwarp();
                for (int t = 0; t < 64; ++t) {
                    unsigned u = d2[(t << 5) | lane];
                    bool act = (u >> (shift + 8)) == prefix;
                    if (__ballot_sync(FULL, act) == 0u) continue;
                    unsigned key = act ? ((u >> shift) & 255u) : 0x100u;
                    unsigned mk = __match_any_sync(FULL, key);
                    if (act && ((mk & below) == 0u))
                        atomicAdd(&hist[key], (unsigned)__popc(mk));
                }
                __syncwarp();
            }
            unsigned sub8 = 0;
#pragma unroll
            for (int b = 0; b < 8; ++b) sub8 += hist[lane * 8 + b];
            unsigned inc = sub8;
#pragma unroll
            for (int off = 1; off < 32; off <<= 1) {
                unsigned v = __shfl_up_sync(FULL, inc, off);
                if (lane >= off) inc += v;
            }
            unsigned exc = inc - sub8;
            unsigned ball = __ballot_sync(FULL, (exc < rk) && (rk <= inc));
            if (ball == 0u) ball = 0x80000000u;   // defensive: never leaves src=-1
            int src = __ffs(ball) - 1;
            unsigned digit = 0, cb = 0;
            if (lane == src) {
                unsigned c = exc;
#pragma unroll
                for (int b = 0; b < 8; ++b) {
                    unsigned hv = hist[lane * 8 + b];
                    if (c + hv >= rk) { digit = (unsigned)(lane * 8 + b); cb = c; break; }
                    c += hv;
                }
            }
            digit = __shfl_sync(FULL, digit, src);
            cb    = __shfl_sync(FULL, cb, src);
            rk -= cb;
            prefix = (prefix << 8) | digit;
        }
        const unsigned tau = prefix;  // k-th smallest key; rk = #ties to take

        // ---- compaction: strict-less first, then rk smallest-index ties ----
        unsigned cnt = 0, ecnt = 0;
        for (int t = 0; t < 64; ++t) {
            int j = (t << 5) | lane;
            unsigned u = d2[j];
            bool lt = u < tau;
            unsigned bl = __ballot_sync(FULL, lt);
            if (lt) {
                unsigned p = cnt + (unsigned)__popc(bl & below);
                if (p < KMAX) cj[p] = (unsigned)j;
            }
            cnt += __popc(bl);
            bool eqf = (u == tau);
            unsigned be = __ballot_sync(FULL, eqf);
            if (eqf) {
                unsigned p = ecnt + (unsigned)__popc(be & below);
                if (p < EQCAP) eqs[p] = (unsigned)j;
            }
            ecnt += __popc(be);
        }
        __syncwarp();
        if (ecnt > EQCAP) ecnt = EQCAP;
        for (unsigned m = lane; m < ecnt; m += 32) {
            unsigned j = eqs[m];
            unsigned r = 0;
            for (unsigned q = 0; q < ecnt; ++q) r += (eqs[q] < j);
            unsigned p = cnt + r;
            if (r < rk && p < KMAX) cj[p] = j;
        }
        __syncwarp();

        // ---- aggregate over the k compacted neighbors ----
        float sum[12], mx[12];
#pragma unroll
        for (int d = 0; d < 12; ++d) { sum[d] = 0.f; mx[d] = -FLT_MAX; }
        for (int m = lane; m < k; m += 32) {
            unsigned j = cj[m] & 2047u;   // masked: reads always in-bounds
            float f = u2f(d2[j]);
            float wgt = __expf(-10.f * fmaxf(f, 0.f));
#pragma unroll
            for (int d = 0; d < 12; ++d) {
                float mv = wgt * hsh[d * NPE + j];
                sum[d] += mv;
                mx[d] = fmaxf(mx[d], mv);
            }
        }
#pragma unroll
        for (int d = 0; d < 12; ++d) {
            float v = sum[d], m = mx[d];
#pragma unroll
            for (int off = 16; off; off >>= 1) {
                v += __shfl_xor_sync(FULL, v, off);
                m = fmaxf(m, __shfl_xor_sync(FULL, m, off));
            }
            sum[d] = v; mx[d] = m;
        }
        if (lane == 0) {
            float4* o = (float4*)&g_agg[(size_t)(base + i) * 24];
            o[0] = make_float4(sum[0] * invk, sum[1] * invk, sum[2] * invk, sum[3] * invk);
            o[1] = make_float4(sum[4] * invk, sum[5] * invk, sum[6] * invk, sum[7] * invk);
            o[2] = make_float4(sum[8] * invk, sum[9] * invk, sum[10] * invk, sum[11] * invk);
            o[3] = make_float4(mx[0], mx[1], mx[2], mx[3]);
            o[4] = make_float4(mx[4], mx[5], mx[6], mx[7]);
            o[5] = make_float4(mx[8], mx[9], mx[10], mx[11]);
        }
        __syncwarp();
    }
}

// ---------------- K3: lin_out1 + lin_out2 + 2-layer post-MLP -> t ----------------
__global__ void k_post(const float* __restrict__ Wg1, const float* __restrict__ Wg2,
                       const float* __restrict__ bg2, const float* __restrict__ Wp1,
                       const float* __restrict__ bp1, const float* __restrict__ Wp2,
                       const float* __restrict__ bp2) {
    __shared__ float wg1[6 * 24], wg2[24 * 24], wp1[27 * 6], wp2[6 * 6];
    __shared__ float sb2[24], sp1[6], sp2[6];
    int tid = threadIdx.x;
    for (int i = tid; i < 144; i += blockDim.x) wg1[i] = Wg1[i];
    for (int i = tid; i < 576; i += blockDim.x) wg2[i] = Wg2[i];
    for (int i = tid; i < 162; i += blockDim.x) wp1[i] = Wp1[i];
    for (int i = tid; i < 36;  i += blockDim.x) wp2[i] = Wp2[i];
    for (int i = tid; i < 24;  i += blockDim.x) sb2[i] = bg2[i];
    for (int i = tid; i < 6;   i += blockDim.x) { sp1[i] = bp1[i]; sp2[i] = bp2[i]; }
    __syncthreads();

    int n = blockIdx.x * blockDim.x + tid;
    if (n >= NTOT) return;
    float xi[6], ag[24], sv[3];
#pragma unroll
    for (int d = 0; d < 6; ++d) xi[d] = g_x[n * 6 + d];
#pragma unroll
    for (int q = 0; q < 24; ++q) ag[q] = g_agg[n * 24 + q];
#pragma unroll
    for (int c = 0; c < 3; ++c) sv[c] = g_s[n * 3 + c];

    float o[24];
#pragma unroll
    for (int c = 0; c < 24; ++c) {
        float a = sb2[c];
#pragma unroll
        for (int d = 0; d < 6; ++d) a = fmaf(xi[d], wg1[d * 24 + c], a);
#pragma unroll
        for (int q = 0; q < 24; ++q) a = fmaf(ag[q], wg2[q * 24 + c], a);
        o[c] = a;
    }
    float t1[6];
#pragma unroll
    for (int d = 0; d < 6; ++d) {
        float a = sp1[d];
#pragma unroll
        for (int c = 0; c < 24; ++c) a = fmaf(o[c], wp1[c * 6 + d], a);
#pragma unroll
        for (int c = 0; c < 3; ++c) a = fmaf(sv[c], wp1[(24 + c) * 6 + d], a);
        t1[d] = eluf(a);
    }
#pragma unroll
    for (int d = 0; d < 6; ++d) {
        float a = sp2[d];
#pragma unroll
        for (int q = 0; q < 6; ++q) a = fmaf(t1[q], wp2[q * 6 + d], a);
        g_t[n * 6 + d] = eluf(a);
    }
}

// ---------------- K4: per-event mean/min/max of t ----------------
__global__ void k_red() {
    __shared__ float ssum[256 * 6], smn[256 * 6], smx[256 * 6];
    int e = blockIdx.x, tid = threadIdx.x;
    int base = e * NPE;
    float s6[6], mn6[6], mx6[6];
#pragma unroll
    for (int d = 0; d < 6; ++d) { s6[d] = 0.f; mn6[d] = FLT_MAX; mx6[d] = -FLT_MAX; }
    for (int i = tid; i < NPE; i += 256) {
#pragma unroll
        for (int d = 0; d < 6; ++d) {
            float v = g_t[(base + i) * 6 + d];
            s6[d] += v; mn6[d] = fminf(mn6[d], v); mx6[d] = fmaxf(mx6[d], v);
        }
    }
#pragma unroll
    for (int d = 0; d < 6; ++d) { ssum[tid * 6 + d] = s6[d]; smn[tid * 6 + d] = mn6[d]; smx[tid * 6 + d] = mx6[d]; }
    __syncthreads();
    for (int s = 128; s > 0; s >>= 1) {
        if (tid < s) {
#pragma unroll
            for (int d = 0; d < 6; ++d) {
                ssum[tid * 6 + d] += ssum[(tid + s) * 6 + d];
                smn[tid * 6 + d] = fminf(smn[tid * 6 + d], smn[(tid + s) * 6 + d]);
                smx[tid * 6 + d] = fmaxf(smx[tid * 6 + d], smx[(tid + s) * 6 + d]);
            }
        }
        __syncthreads();
    }
    if (tid == 0) {
#pragma unroll
        for (int d = 0; d < 6; ++d) {
            g_stats[e * 18 + d]      = ssum[d] * (1.f / (float)NPE);
            g_stats[e * 18 + 6 + d]  = smn[d];
            g_stats[e * 18 + 12 + d] = smx[d];
        }
    }
}

// ---------------- K5: global-exchange dense + elu -> new x (+ next-layer proj) ----------------
__global__ void k_ex(int layer, int do_proj,
                     const float* __restrict__ Wex, const float* __restrict__ bex,
                     const float* __restrict__ Ws, const float* __restrict__ bs,
                     const float* __restrict__ Wh, const float* __restrict__ bh) {
    int n = blockIdx.x * blockDim.x + threadIdx.x;
    if (n >= NTOT) return;
    int e = n >> 11;
    float ex[24];
#pragma unroll
    for (int c = 0; c < 18; ++c) ex[c] = g_stats[e * 18 + c];
#pragma unroll
    for (int d = 0; d < 6; ++d) ex[18 + d] = g_t[n * 6 + d];
    float xv[6];
#pragma unroll
    for (int d = 0; d < 6; ++d) {
        float a = bex[d];
#pragma unroll
        for (int c = 0; c < 24; ++c) a = fmaf(ex[c], Wex[c * 6 + d], a);
        float v = eluf(a);
        xv[d] = v;
        g_x[n * 6 + d] = v;
        g_feats[n * 24 + layer * 6 + d] = v;
    }
    if (do_proj) {
#pragma unroll
        for (int sp = 0; sp < 3; ++sp) {
            float a = bs[sp];
#pragma unroll
            for (int d = 0; d < 6; ++d) a = fmaf(xv[d], Ws[d * 3 + sp], a);
            g_s[n * 3 + sp] = a;
        }
#pragma unroll
        for (int p = 0; p < 12; ++p) {
            float a = bh[p];
#pragma unroll
            for (int d = 0; d < 6; ++d) a = fmaf(xv[d], Wh[d * 12 + p], a);
            g_h[n * 12 + p] = a;
        }
    }
}

// ---------------- K6: output head ----------------
#define H_WD0 0
#define H_BD0 144
#define H_WD  150
#define H_BD  258
#define H_WH1 276
#define H_BH1 660
#define H_WH2 724
#define H_BH2 4820
#define H_WH3 4884
#define H_BH3 8980
#define H_WC  9044
#define H_BC  10964
#define H_WB  10994
#define H_BB  11058
#define H_TOT 11059

__global__ void __launch_bounds__(128) k_head(
    const float* __restrict__ Wd0, const float* __restrict__ bd0,
    const float* __restrict__ Wd,  const float* __restrict__ bd,
    const float* __restrict__ Wh1, const float* __restrict__ bh1,
    const float* __restrict__ Wh2, const float* __restrict__ bh2,
    const float* __restrict__ Wh3, const float* __restrict__ bh3,
    const float* __restrict__ Wc,  const float* __restrict__ bc,
    const float* __restrict__ Wb,  const float* __restrict__ bb,
    float* __restrict__ out) {
    __shared__ float S[H_TOT];
    int tid = threadIdx.x;
    for (int i = tid; i < 144;  i += 128) S[H_WD0 + i] = Wd0[i];
    for (int i = tid; i < 6;    i += 128) S[H_BD0 + i] = bd0[i];
    for (int i = tid; i < 108;  i += 128) S[H_WD + i]  = Wd[i];
    for (int i = tid; i < 18;   i += 128) S[H_BD + i]  = bd[i];
    for (int i = tid; i < 384;  i += 128) S[H_WH1 + i] = Wh1[i];
    for (int i = tid; i < 64;   i += 128) S[H_BH1 + i] = bh1[i];
    for (int i = tid; i < 4096; i += 128) S[H_WH2 + i] = Wh2[i];
    for (int i = tid; i < 64;   i += 128) S[H_BH2 + i] = bh2[i];
    for (int i = tid; i < 4096; i += 128) S[H_WH3 + i] = Wh3[i];
    for (int i = tid; i < 64;   i += 128) S[H_BH3 + i] = bh3[i];
    for (int i = tid; i < 1920; i += 128) S[H_WC + i]  = Wc[i];
    for (int i = tid; i < 30;   i += 128) S[H_BC + i]  = bc[i];
    for (int i = tid; i < 64;   i += 128) S[H_WB + i]  = Wb[i];
    for (int i = tid; i < 1;    i += 128) S[H_BB + i]  = bb[i];
    __syncthreads();

    int n = blockIdx.x * 128 + tid;
    if (n >= NTOT) return;

    float f24[24];
#pragma unroll
    for (int c = 0; c < 24; ++c) f24[c] = g_feats[n * 24 + c];

    float y6[6];
#pragma unroll
    for (int d = 0; d < 6; ++d) {
        float a = S[H_BD0 + d];
#pragma unroll
        for (int c = 0; c < 24; ++c) a = fmaf(f24[c], S[H_WD0 + c * 6 + d], a);
        y6[d] = eluf(a);
    }
    for (int j = 0; j < 3; ++j) {
        float z6[6];
#pragma unroll
        for (int d = 0; d < 6; ++d) {
            float a = S[H_BD + j * 6 + d];
#pragma unroll
            for (int c = 0; c < 6; ++c) a = fmaf(y6[c], S[H_WD + j * 36 + c * 6 + d], a);
            z6[d] = eluf(a);
        }
#pragma unroll
        for (int d = 0; d < 6; ++d) y6[d] = z6[d];
    }

    float ya[64];
#pragma unroll
    for (int d = 0; d < 64; ++d) ya[d] = S[H_BH1 + d];
    for (int c = 0; c < 6; ++c) {
        float v = y6[c];
#pragma unroll
        for (int d = 0; d < 64; ++d) ya[d] = fmaf(v, S[H_WH1 + c * 64 + d], ya[d]);
    }
#pragma unroll
    for (int d = 0; d < 64; ++d) ya[d] = eluf(ya[d]);

    float yc[64];
#pragma unroll
    for (int d = 0; d < 64; ++d) yc[d] = S[H_BH3 + d];
    for (int c = 0; c < 64; ++c) {
        float a = S[H_BH2 + c];
#pragma unroll
        for (int q = 0; q < 64; ++q) a = fmaf(ya[q], S[H_WH2 + q * 64 + c], a);
        a = eluf(a);
#pragma unroll
        for (int d = 0; d < 64; ++d) yc[d] = fmaf(a, S[H_WH3 + c * 64 + d], yc[d]);
    }

    float o[30];
#pragma unroll
    for (int c = 0; c < 30; ++c) o[c] = S[H_BC + c];
    float ob = S[H_BB];
    for (int q = 0; q < 64; ++q) {
        float v = yc[q];
#pragma unroll
        for (int c = 0; c < 30; ++c) o[c] = fmaf(v, S[H_WC + q * 30 + c], o[c]);
        ob = fmaf(v, S[H_WB + q], ob);
    }
#pragma unroll
    for (int c = 0; c < 30; ++c) out[n * 31 + c] = o[c];
    out[n * 31 + 30] = ob;
}

// ---------------- launch ----------------
extern "C" void kernel_launch(void* const* d_in, const int* in_sizes, int n_in,
                              void* d_out, int out_size) {
    const float* X    = (const float*)d_in[0];
    const float* Win  = (const float*)d_in[1];
    const float* Ws   = (const float*)d_in[2];
    const float* bs   = (const float*)d_in[3];
    const float* Wh   = (const float*)d_in[4];
    const float* bh   = (const float*)d_in[5];
    const float* Wg1  = (const float*)d_in[6];
    const float* Wg2  = (const float*)d_in[7];
    const float* bg2  = (const float*)d_in[8];
    const float* Wp1  = (const float*)d_in[9];
    const float* bp1  = (const float*)d_in[10];
    const float* Wp2  = (const float*)d_in[11];
    const float* bp2  = (const float*)d_in[12];
    const float* Wex  = (const float*)d_in[13];
    const float* bex  = (const float*)d_in[14];
    const float* Wd0  = (const float*)d_in[15];
    const float* bd0  = (const float*)d_in[16];
    const float* Wd   = (const float*)d_in[17];
    const float* bd   = (const float*)d_in[18];
    const float* Wh1  = (const float*)d_in[19];
    const float* bh1  = (const float*)d_in[20];
    const float* Wh2  = (const float*)d_in[21];
    const float* bh2  = (const float*)d_in[22];
    const float* Wh3  = (const float*)d_in[23];
    const float* bh3  = (const float*)d_in[24];
    const float* Wc   = (const float*)d_in[25];
    const float* bc   = (const float*)d_in[26];
    const float* Wb   = (const float*)d_in[27];
    const float* bb   = (const float*)d_in[28];

    cudaFuncSetAttribute(k_grav, cudaFuncAttributeMaxDynamicSharedMemorySize,
                         (int)GRAV_SMEM_BYTES);

    const int KS[4] = {16, 128, 16, 256};

    k_embed<<<NTOT / 256, 256>>>(X, Win, Ws, bs, Wh, bh);
    for (int i = 0; i < 4; ++i) {
        k_grav<<<dim3(8, NB), GR_THREADS, GRAV_SMEM_BYTES>>>(KS[i]);
        k_post<<<NTOT / 256, 256>>>(Wg1 + i * 144, Wg2 + i * 576, bg2 + i * 24,
                                    Wp1 + i * 162, bp1 + i * 6, Wp2 + i * 36, bp2 + i * 6);
        k_red<<<NB, 256>>>();
        int nx = (i + 1) & 3;      // valid offsets even when do_proj==0
        k_ex<<<NTOT / 256, 256>>>(i, (i < 3) ? 1 : 0, Wex + i * 144, bex + i * 6,
                                  Ws + nx * 18, bs + nx * 3, Wh + nx * 72, bh + nx * 12);
    }
    k_head<<<NTOT / 128, 128>>>(Wd0, bd0, Wd, bd, Wh1, bh1, Wh2, bh2, Wh3, bh3,
                                Wc, bc, Wb, bb, (float*)d_out);
}

// round 14
// speedup vs baseline: 1.5239x; 1.5239x over previous
#include <cuda_runtime.h>
#include <math.h>
#include <float.h>

// ---------------- problem constants ----------------
#define NTOT 32768     // B*NP
#define NB   16
#define NPE  2048      // nodes per event

// ---------------- scratch (device globals; no allocations) ----------------
__device__ __align__(16) float g_x[NTOT * 6];
__device__ __align__(16) float g_s[NTOT * 3];
__device__ __align__(16) float g_h[NTOT * 12];
__device__ __align__(16) float g_agg[NTOT * 24];
__device__ __align__(16) float g_t[NTOT * 6];
__device__ __align__(16) float g_feats[NTOT * 24];
__device__ __align__(16) float g_stats[NB * 18];

// ---------------- helpers ----------------
__device__ __forceinline__ float dot3(float a0, float a1, float a2,
                                      float b0, float b1, float b2) {
    return fmaf(a2, b2, fmaf(a1, b1, a0 * b0));
}
__device__ __forceinline__ float eluf(float x) { return x > 0.f ? x : expm1f(x); }
__device__ __forceinline__ unsigned f2u(float f) {
    unsigned u = __float_as_uint(f);
    return (u & 0x80000000u) ? ~u : (u | 0x80000000u);
}

// ---------------- K0: input embedding + layer-0 s/h projection ----------------
__global__ void k_embed(const float* __restrict__ X, const float* __restrict__ Win,
                        const float* __restrict__ Ws, const float* __restrict__ bs,
                        const float* __restrict__ Wh, const float* __restrict__ bh) {
    int n = blockIdx.x * blockDim.x + threadIdx.x;
    if (n >= NTOT) return;
    float xi[9];
#pragma unroll
    for (int q = 0; q < 9; ++q) xi[q] = X[n * 9 + q];
    float xv[6];
#pragma unroll
    for (int d = 0; d < 6; ++d) {
        float a = 0.f;
#pragma unroll
        for (int q = 0; q < 9; ++q) a = fmaf(xi[q], Win[q * 6 + d], a);
        xv[d] = a;
        g_x[n * 6 + d] = a;
    }
#pragma unroll
    for (int sp = 0; sp < 3; ++sp) {
        float a = bs[sp];
#pragma unroll
        for (int d = 0; d < 6; ++d) a = fmaf(xv[d], Ws[d * 3 + sp], a);
        g_s[n * 3 + sp] = a;
    }
#pragma unroll
    for (int p = 0; p < 12; ++p) {
        float a = bh[p];
#pragma unroll
        for (int d = 0; d < 6; ++d) a = fmaf(xv[d], Wh[d * 12 + p], a);
        g_h[n * 12 + p] = a;
    }
}

// ---------------- K2: GravNet kNN + weighted mean/max aggregation ----------------
// Warp-per-node. 2048 distance keys live in registers (64/lane).
// Exact k-th key via bitwise binary search with warp-reduced counts:
// no shared scans, no atomics, no match ops in the hot path.
#define GR_THREADS 256
#define GR_WARPS   8
#define KMAX       256
#define EQCAP      64
// floats: s4 (2048 float4 = 8192) + hsh (12*2048 = 24576) = 32768
// u32 per warp: cj KMAX + eqs EQCAP
#define GRAV_WORDS (32768u + GR_WARPS * (KMAX + EQCAP))
#define GRAV_SMEM_BYTES (GRAV_WORDS * 4u)

__global__ void __launch_bounds__(GR_THREADS, 1) k_grav(int k) {
    extern __shared__ float sm[];
    float4* s4  = (float4*)sm;               // [2048] (s0,s1,s2,|s|^2)
    float*  hsh = sm + 8192;                 // [12][2048]
    unsigned* cjall  = (unsigned*)(sm + 32768);
    unsigned* eqall  = cjall + GR_WARPS * KMAX;

    const int e = blockIdx.y, sub = blockIdx.x;
    const int tid = threadIdx.x, w = tid >> 5, lane = tid & 31;
    const int base = e * NPE;
    const unsigned FULL = 0xffffffffu;
    const unsigned below = (1u << lane) - 1u;

    // stage s (float4 with |s|^2 in .w)
    for (int i = tid; i < NPE; i += GR_THREADS) {
        float a = g_s[(base + i) * 3 + 0];
        float b = g_s[(base + i) * 3 + 1];
        float c = g_s[(base + i) * 3 + 2];
        s4[i] = make_float4(a, b, c, dot3(a, b, c, a, b, c));
    }
    // stage h transposed to [d][node]
    for (int idx = tid; idx < NPE * 12; idx += GR_THREADS) {
        int i = idx / 12, d = idx - i * 12;
        hsh[d * NPE + i] = g_h[base * 12 + idx];
    }
    for (int i = tid; i < (int)(GR_WARPS * KMAX); i += GR_THREADS) cjall[i] = 0u;
    __syncthreads();

    unsigned* cj  = cjall + w * KMAX;
    unsigned* eqs = eqall + w * EQCAP;
    const float invk = 1.f / (float)k;
    const unsigned uk = (unsigned)k;

    for (int nn = 0; nn < 32; ++nn) {
        const int i = sub * 256 + w * 32 + nn;
        const float4 si = s4[i];

        // ---- distances -> ordered uint keys, kept in registers ----
        unsigned key[64];
#pragma unroll
        for (int t = 0; t < 64; ++t) {
            int j = (t << 5) | lane;
            float4 sj = s4[j];
            float dd = (si.w + sj.w) - 2.f * dot3(si.x, si.y, si.z, sj.x, sj.y, sj.z);
            key[t] = f2u(dd);
        }

        // ---- common-prefix detection (skip bits where all 2048 keys agree) ----
        unsigned av = 0xffffffffu, ov = 0u;
#pragma unroll
        for (int t = 0; t < 64; ++t) { av &= key[t]; ov |= key[t]; }
#pragma unroll
        for (int off = 16; off; off >>= 1) {
            av &= __shfl_xor_sync(FULL, av, off);
            ov |= __shfl_xor_sync(FULL, ov, off);
        }
        unsigned diff = av ^ ov;
        unsigned tau;
        if (diff == 0u) {
            tau = av;  // all keys identical
        } else {
            int hb = 31 - __clz(diff);
            unsigned mask = (hb == 31) ? 0xffffffffu : ((2u << hb) - 1u);
            unsigned p = av & ~mask;   // shared high bits
            for (int bit = hb; bit >= 0; --bit) {
                unsigned trial = p + (1u << bit);
                unsigned c = 0;
#pragma unroll
                for (int t = 0; t < 64; ++t) c += (key[t] < trial) ? 1u : 0u;
#pragma unroll
                for (int off = 16; off; off >>= 1)
                    c += __shfl_xor_sync(FULL, c, off);
                if (c < uk) p = trial;   // k-th smallest >= trial -> bit is 1
            }
            tau = p;   // exact k-th smallest key
        }

        // ---- compaction: strict-less first, then rk smallest-index ties ----
        unsigned cnt = 0, ecnt = 0;
#pragma unroll
        for (int t = 0; t < 64; ++t) {
            int j = (t << 5) | lane;
            unsigned u = key[t];
            bool lt = u < tau;
            unsigned bl = __ballot_sync(FULL, lt);
            if (lt) {
                unsigned p = cnt + (unsigned)__popc(bl & below);
                if (p < KMAX) cj[p] = (unsigned)j;
            }
            cnt += __popc(bl);
            bool eqf = (u == tau);
            unsigned be = __ballot_sync(FULL, eqf);
            if (eqf) {
                unsigned p = ecnt + (unsigned)__popc(be & below);
                if (p < EQCAP) eqs[p] = (unsigned)j;
            }
            ecnt += __popc(be);
        }
        __syncwarp();
        unsigned rk = (uk > cnt) ? (uk - cnt) : 0u;   // ties to take
        if (ecnt > EQCAP) ecnt = EQCAP;
        for (unsigned m = lane; m < ecnt; m += 32) {
            unsigned j = eqs[m];
            unsigned r = 0;
            for (unsigned q = 0; q < ecnt; ++q) r += (eqs[q] < j);
            unsigned p = cnt + r;
            if (r < rk && p < KMAX) cj[p] = j;
        }
        __syncwarp();

        // ---- aggregate over the k selected neighbors (recompute d2) ----
        float sum[12], mx[12];
#pragma unroll
        for (int d = 0; d < 12; ++d) { sum[d] = 0.f; mx[d] = -FLT_MAX; }
        for (int m = lane; m < k; m += 32) {
            unsigned j = cj[m] & 2047u;   // masked: reads always in-bounds
            float4 sj = s4[j];
            float dd = (si.w + sj.w) - 2.f * dot3(si.x, si.y, si.z, sj.x, sj.y, sj.z);
            float wgt = __expf(-10.f * fmaxf(dd, 0.f));
#pragma unroll
            for (int d = 0; d < 12; ++d) {
                float mv = wgt * hsh[d * NPE + j];
                sum[d] += mv;
                mx[d] = fmaxf(mx[d], mv);
            }
        }
#pragma unroll
        for (int d = 0; d < 12; ++d) {
            float v = sum[d], m = mx[d];
#pragma unroll
            for (int off = 16; off; off >>= 1) {
                v += __shfl_xor_sync(FULL, v, off);
                m = fmaxf(m, __shfl_xor_sync(FULL, m, off));
            }
            sum[d] = v; mx[d] = m;
        }
        if (lane == 0) {
            float4* o = (float4*)&g_agg[(size_t)(base + i) * 24];
            o[0] = make_float4(sum[0] * invk, sum[1] * invk, sum[2] * invk, sum[3] * invk);
            o[1] = make_float4(sum[4] * invk, sum[5] * invk, sum[6] * invk, sum[7] * invk);
            o[2] = make_float4(sum[8] * invk, sum[9] * invk, sum[10] * invk, sum[11] * invk);
            o[3] = make_float4(mx[0], mx[1], mx[2], mx[3]);
            o[4] = make_float4(mx[4], mx[5], mx[6], mx[7]);
            o[5] = make_float4(mx[8], mx[9], mx[10], mx[11]);
        }
        __syncwarp();
    }
}

// ---------------- K3: lin_out1 + lin_out2 + 2-layer post-MLP -> t ----------------
__global__ void k_post(const float* __restrict__ Wg1, const float* __restrict__ Wg2,
                       const float* __restrict__ bg2, const float* __restrict__ Wp1,
                       const float* __restrict__ bp1, const float* __restrict__ Wp2,
                       const float* __restrict__ bp2) {
    __shared__ float wg1[6 * 24], wg2[24 * 24], wp1[27 * 6], wp2[6 * 6];
    __shared__ float sb2[24], sp1[6], sp2[6];
    int tid = threadIdx.x;
    for (int i = tid; i < 144; i += blockDim.x) wg1[i] = Wg1[i];
    for (int i = tid; i < 576; i += blockDim.x) wg2[i] = Wg2[i];
    for (int i = tid; i < 162; i += blockDim.x) wp1[i] = Wp1[i];
    for (int i = tid; i < 36;  i += blockDim.x) wp2[i] = Wp2[i];
    for (int i = tid; i < 24;  i += blockDim.x) sb2[i] = bg2[i];
    for (int i = tid; i < 6;   i += blockDim.x) { sp1[i] = bp1[i]; sp2[i] = bp2[i]; }
    __syncthreads();

    int n = blockIdx.x * blockDim.x + tid;
    if (n >= NTOT) return;
    float xi[6], ag[24], sv[3];
#pragma unroll
    for (int d = 0; d < 6; ++d) xi[d] = g_x[n * 6 + d];
#pragma unroll
    for (int q = 0; q < 24; ++q) ag[q] = g_agg[n * 24 + q];
#pragma unroll
    for (int c = 0; c < 3; ++c) sv[c] = g_s[n * 3 + c];

    float o[24];
#pragma unroll
    for (int c = 0; c < 24; ++c) {
        float a = sb2[c];
#pragma unroll
        for (int d = 0; d < 6; ++d) a = fmaf(xi[d], wg1[d * 24 + c], a);
#pragma unroll
        for (int q = 0; q < 24; ++q) a = fmaf(ag[q], wg2[q * 24 + c], a);
        o[c] = a;
    }
    float t1[6];
#pragma unroll
    for (int d = 0; d < 6; ++d) {
        float a = sp1[d];
#pragma unroll
        for (int c = 0; c < 24; ++c) a = fmaf(o[c], wp1[c * 6 + d], a);
#pragma unroll
        for (int c = 0; c < 3; ++c) a = fmaf(sv[c], wp1[(24 + c) * 6 + d], a);
        t1[d] = eluf(a);
    }
#pragma unroll
    for (int d = 0; d < 6; ++d) {
        float a = sp2[d];
#pragma unroll
        for (int q = 0; q < 6; ++q) a = fmaf(t1[q], wp2[q * 6 + d], a);
        g_t[n * 6 + d] = eluf(a);
    }
}

// ---------------- K4: per-event mean/min/max of t ----------------
__global__ void k_red() {
    __shared__ float ssum[256 * 6], smn[256 * 6], smx[256 * 6];
    int e = blockIdx.x, tid = threadIdx.x;
    int base = e * NPE;
    float s6[6], mn6[6], mx6[6];
#pragma unroll
    for (int d = 0; d < 6; ++d) { s6[d] = 0.f; mn6[d] = FLT_MAX; mx6[d] = -FLT_MAX; }
    for (int i = tid; i < NPE; i += 256) {
#pragma unroll
        for (int d = 0; d < 6; ++d) {
            float v = g_t[(base + i) * 6 + d];
            s6[d] += v; mn6[d] = fminf(mn6[d], v); mx6[d] = fmaxf(mx6[d], v);
        }
    }
#pragma unroll
    for (int d = 0; d < 6; ++d) { ssum[tid * 6 + d] = s6[d]; smn[tid * 6 + d] = mn6[d]; smx[tid * 6 + d] = mx6[d]; }
    __syncthreads();
    for (int s = 128; s > 0; s >>= 1) {
        if (tid < s) {
#pragma unroll
            for (int d = 0; d < 6; ++d) {
                ssum[tid * 6 + d] += ssum[(tid + s) * 6 + d];
                smn[tid * 6 + d] = fminf(smn[tid * 6 + d], smn[(tid + s) * 6 + d]);
                smx[tid * 6 + d] = fmaxf(smx[tid * 6 + d], smx[(tid + s) * 6 + d]);
            }
        }
        __syncthreads();
    }
    if (tid == 0) {
#pragma unroll
        for (int d = 0; d < 6; ++d) {
            g_stats[e * 18 + d]      = ssum[d] * (1.f / (float)NPE);
            g_stats[e * 18 + 6 + d]  = smn[d];
            g_stats[e * 18 + 12 + d] = smx[d];
        }
    }
}

// ---------------- K5: global-exchange dense + elu -> new x (+ next-layer proj) ----------------
__global__ void k_ex(int layer, int do_proj,
                     const float* __restrict__ Wex, const float* __restrict__ bex,
                     const float* __restrict__ Ws, const float* __restrict__ bs,
                     const float* __restrict__ Wh, const float* __restrict__ bh) {
    int n = blockIdx.x * blockDim.x + threadIdx.x;
    if (n >= NTOT) return;
    int e = n >> 11;
    float ex[24];
#pragma unroll
    for (int c = 0; c < 18; ++c) ex[c] = g_stats[e * 18 + c];
#pragma unroll
    for (int d = 0; d < 6; ++d) ex[18 + d] = g_t[n * 6 + d];
    float xv[6];
#pragma unroll
    for (int d = 0; d < 6; ++d) {
        float a = bex[d];
#pragma unroll
        for (int c = 0; c < 24; ++c) a = fmaf(ex[c], Wex[c * 6 + d], a);
        float v = eluf(a);
        xv[d] = v;
        g_x[n * 6 + d] = v;
        g_feats[n * 24 + layer * 6 + d] = v;
    }
    if (do_proj) {
#pragma unroll
        for (int sp = 0; sp < 3; ++sp) {
            float a = bs[sp];
#pragma unroll
            for (int d = 0; d < 6; ++d) a = fmaf(xv[d], Ws[d * 3 + sp], a);
            g_s[n * 3 + sp] = a;
        }
#pragma unroll
        for (int p = 0; p < 12; ++p) {
            float a = bh[p];
#pragma unroll
            for (int d = 0; d < 6; ++d) a = fmaf(xv[d], Wh[d * 12 + p], a);
            g_h[n * 12 + p] = a;
        }
    }
}

// ---------------- K6: output head ----------------
#define H_WD0 0
#define H_BD0 144
#define H_WD  150
#define H_BD  258
#define H_WH1 276
#define H_BH1 660
#define H_WH2 724
#define H_BH2 4820
#define H_WH3 4884
#define H_BH3 8980
#define H_WC  9044
#define H_BC  10964
#define H_WB  10994
#define H_BB  11058
#define H_TOT 11059

__global__ void __launch_bounds__(128) k_head(
    const float* __restrict__ Wd0, const float* __restrict__ bd0,
    const float* __restrict__ Wd,  const float* __restrict__ bd,
    const float* __restrict__ Wh1, const float* __restrict__ bh1,
    const float* __restrict__ Wh2, const float* __restrict__ bh2,
    const float* __restrict__ Wh3, const float* __restrict__ bh3,
    const float* __restrict__ Wc,  const float* __restrict__ bc,
    const float* __restrict__ Wb,  const float* __restrict__ bb,
    float* __restrict__ out) {
    __shared__ float S[H_TOT];
    int tid = threadIdx.x;
    for (int i = tid; i < 144;  i += 128) S[H_WD0 + i] = Wd0[i];
    for (int i = tid; i < 6;    i += 128) S[H_BD0 + i] = bd0[i];
    for (int i = tid; i < 108;  i += 128) S[H_WD + i]  = Wd[i];
    for (int i = tid; i < 18;   i += 128) S[H_BD + i]  = bd[i];
    for (int i = tid; i < 384;  i += 128) S[H_WH1 + i] = Wh1[i];
    for (int i = tid; i < 64;   i += 128) S[H_BH1 + i] = bh1[i];
    for (int i = tid; i < 4096; i += 128) S[H_WH2 + i] = Wh2[i];
    for (int i = tid; i < 64;   i += 128) S[H_BH2 + i] = bh2[i];
    for (int i = tid; i < 4096; i += 128) S[H_WH3 + i] = Wh3[i];
    for (int i = tid; i < 64;   i += 128) S[H_BH3 + i] = bh3[i];
    for (int i = tid; i < 1920; i += 128) S[H_WC + i]  = Wc[i];
    for (int i = tid; i < 30;   i += 128) S[H_BC + i]  = bc[i];
    for (int i = tid; i < 64;   i += 128) S[H_WB + i]  = Wb[i];
    for (int i = tid; i < 1;    i += 128) S[H_BB + i]  = bb[i];
    __syncthreads();

    int n = blockIdx.x * 128 + tid;
    if (n >= NTOT) return;

    float f24[24];
#pragma unroll
    for (int c = 0; c < 24; ++c) f24[c] = g_feats[n * 24 + c];

    float y6[6];
#pragma unroll
    for (int d = 0; d < 6; ++d) {
        float a = S[H_BD0 + d];
#pragma unroll
        for (int c = 0; c < 24; ++c) a = fmaf(f24[c], S[H_WD0 + c * 6 + d], a);
        y6[d] = eluf(a);
    }
    for (int j = 0; j < 3; ++j) {
        float z6[6];
#pragma unroll
        for (int d = 0; d < 6; ++d) {
            float a = S[H_BD + j * 6 + d];
#pragma unroll
            for (int c = 0; c < 6; ++c) a = fmaf(y6[c], S[H_WD + j * 36 + c * 6 + d], a);
            z6[d] = eluf(a);
        }
#pragma unroll
        for (int d = 0; d < 6; ++d) y6[d] = z6[d];
    }

    float ya[64];
#pragma unroll
    for (int d = 0; d < 64; ++d) ya[d] = S[H_BH1 + d];
    for (int c = 0; c < 6; ++c) {
        float v = y6[c];
#pragma unroll
        for (int d = 0; d < 64; ++d) ya[d] = fmaf(v, S[H_WH1 + c * 64 + d], ya[d]);
    }
#pragma unroll
    for (int d = 0; d < 64; ++d) ya[d] = eluf(ya[d]);

    float yc[64];
#pragma unroll
    for (int d = 0; d < 64; ++d) yc[d] = S[H_BH3 + d];
    for (int c = 0; c < 64; ++c) {
        float a = S[H_BH2 + c];
#pragma unroll
        for (int q = 0; q < 64; ++q) a = fmaf(ya[q], S[H_WH2 + q * 64 + c], a);
        a = eluf(a);
#pragma unroll
        for (int d = 0; d < 64; ++d) yc[d] = fmaf(a, S[H_WH3 + c * 64 + d], yc[d]);
    }

    float o[30];
#pragma unroll
    for (int c = 0; c < 30; ++c) o[c] = S[H_BC + c];
    float ob = S[H_BB];
    for (int q = 0; q < 64; ++q) {
        float v = yc[q];
#pragma unroll
        for (int c = 0; c < 30; ++c) o[c] = fmaf(v, S[H_WC + q * 30 + c], o[c]);
        ob = fmaf(v, S[H_WB + q], ob);
    }
#pragma unroll
    for (int c = 0; c < 30; ++c) out[n * 31 + c] = o[c];
    out[n * 31 + 30] = ob;
}

// ---------------- launch ----------------
extern "C" void kernel_launch(void* const* d_in, const int* in_sizes, int n_in,
                              void* d_out, int out_size) {
    const float* X    = (const float*)d_in[0];
    const float* Win  = (const float*)d_in[1];
    const float* Ws   = (const float*)d_in[2];
    const float* bs   = (const float*)d_in[3];
    const float* Wh   = (const float*)d_in[4];
    const float* bh   = (const float*)d_in[5];
    const float* Wg1  = (const float*)d_in[6];
    const float* Wg2  = (const float*)d_in[7];
    const float* bg2  = (const float*)d_in[8];
    const float* Wp1  = (const float*)d_in[9];
    const float* bp1  = (const float*)d_in[10];
    const float* Wp2  = (const float*)d_in[11];
    const float* bp2  = (const float*)d_in[12];
    const float* Wex  = (const float*)d_in[13];
    const float* bex  = (const float*)d_in[14];
    const float* Wd0  = (const float*)d_in[15];
    const float* bd0  = (const float*)d_in[16];
    const float* Wd   = (const float*)d_in[17];
    const float* bd   = (const float*)d_in[18];
    const float* Wh1  = (const float*)d_in[19];
    const float* bh1  = (const float*)d_in[20];
    const float* Wh2  = (const float*)d_in[21];
    const float* bh2  = (const float*)d_in[22];
    const float* Wh3  = (const float*)d_in[23];
    const float* bh3  = (const float*)d_in[24];
    const float* Wc   = (const float*)d_in[25];
    const float* bc   = (const float*)d_in[26];
    const float* Wb   = (const float*)d_in[27];
    const float* bb   = (const float*)d_in[28];

    cudaFuncSetAttribute(k_grav, cudaFuncAttributeMaxDynamicSharedMemorySize,
                         (int)GRAV_SMEM_BYTES);

    const int KS[4] = {16, 128, 16, 256};

    k_embed<<<NTOT / 256, 256>>>(X, Win, Ws, bs, Wh, bh);
    for (int i = 0; i < 4; ++i) {
        k_grav<<<dim3(8, NB), GR_THREADS, GRAV_SMEM_BYTES>>>(KS[i]);
        k_post<<<NTOT / 256, 256>>>(Wg1 + i * 144, Wg2 + i * 576, bg2 + i * 24,
                                    Wp1 + i * 162, bp1 + i * 6, Wp2 + i * 36, bp2 + i * 6);
        k_red<<<NB, 256>>>();
        int nx = (i + 1) & 3;      // valid offsets even when do_proj==0
        k_ex<<<NTOT / 256, 256>>>(i, (i < 3) ? 1 : 0, Wex + i * 144, bex + i * 6,
                                  Ws + nx * 18, bs + nx * 3, Wh + nx * 72, bh + nx * 12);
    }
    k_head<<<NTOT / 128, 128>>>(Wd0, bd0, Wd, bd, Wh1, bh1, Wh2, bh2, Wh3, bh3,
                                Wc, bc, Wb, bb, (float*)d_out);
}

// round 16
// speedup vs baseline: 2.4425x; 1.6028x over previous
#include <cuda_runtime.h>
#include <math.h>
#include <float.h>

// ---------------- problem constants ----------------
#define NTOT 32768     // B*NP
#define NB   16
#define NPE  2048      // nodes per event

// ---------------- scratch (device globals; no allocations) ----------------
__device__ __align__(16) float g_x[NTOT * 6];
__device__ __align__(16) float g_s[NTOT * 3];
__device__ __align__(16) float g_h[NTOT * 12];
__device__ __align__(16) float g_agg[NTOT * 24];
__device__ __align__(16) float g_t[NTOT * 6];
__device__ __align__(16) float g_feats[NTOT * 24];
__device__ __align__(16) float g_stats[NB * 18];

// ---------------- helpers ----------------
__device__ __forceinline__ float dot3(float a0, float a1, float a2,
                                      float b0, float b1, float b2) {
    return fmaf(a2, b2, fmaf(a1, b1, a0 * b0));
}
__device__ __forceinline__ float eluf(float x) { return x > 0.f ? x : expm1f(x); }
__device__ __forceinline__ unsigned f2u(float f) {
    unsigned u = __float_as_uint(f);
    return (u & 0x80000000u) ? ~u : (u | 0x80000000u);
}

// ---------------- K0: input embedding + layer-0 s/h projection ----------------
__global__ void k_embed(const float* __restrict__ X, const float* __restrict__ Win,
                        const float* __restrict__ Ws, const float* __restrict__ bs,
                        const float* __restrict__ Wh, const float* __restrict__ bh) {
    int n = blockIdx.x * blockDim.x + threadIdx.x;
    if (n >= NTOT) return;
    float xi[9];
#pragma unroll
    for (int q = 0; q < 9; ++q) xi[q] = X[n * 9 + q];
    float xv[6];
#pragma unroll
    for (int d = 0; d < 6; ++d) {
        float a = 0.f;
#pragma unroll
        for (int q = 0; q < 9; ++q) a = fmaf(xi[q], Win[q * 6 + d], a);
        xv[d] = a;
        g_x[n * 6 + d] = a;
    }
#pragma unroll
    for (int sp = 0; sp < 3; ++sp) {
        float a = bs[sp];
#pragma unroll
        for (int d = 0; d < 6; ++d) a = fmaf(xv[d], Ws[d * 3 + sp], a);
        g_s[n * 3 + sp] = a;
    }
#pragma unroll
    for (int p = 0; p < 12; ++p) {
        float a = bh[p];
#pragma unroll
        for (int d = 0; d < 6; ++d) a = fmaf(xv[d], Wh[d * 12 + p], a);
        g_h[n * 12 + p] = a;
    }
}

// ---------------- K2: GravNet kNN + weighted mean/max aggregation ----------------
// Warp-per-node, 4 nodes/warp. 2048 distance keys in registers (64/lane).
// Exact k-th key via bitwise binary search with redux-reduced counts.
// h is read from L2 (g_h) during aggregation -> smem 42KB -> 2 blocks/SM,
// 16 warps/SM (4/SMSP) to hide SHFL/ballot serial latency.
#define GR_THREADS 256
#define GR_WARPS   8
#define NPW        4           // nodes per warp
#define KMAX       256
#define EQCAP      64
// floats: s4 (2048 float4 = 8192 floats = 32KB)
// u32 per warp: cj KMAX + eqs EQCAP
#define GRAV_WORDS (8192u + GR_WARPS * (KMAX + EQCAP))
#define GRAV_SMEM_BYTES (GRAV_WORDS * 4u)

__global__ void __launch_bounds__(GR_THREADS, 2) k_grav(int k) {
    extern __shared__ float sm[];
    float4* s4  = (float4*)sm;               // [2048] (s0,s1,s2,|s|^2)
    unsigned* cjall  = (unsigned*)(sm + 8192);
    unsigned* eqall  = cjall + GR_WARPS * KMAX;

    const int e = blockIdx.y, sub = blockIdx.x;
    const int tid = threadIdx.x, w = tid >> 5, lane = tid & 31;
    const int base = e * NPE;
    const unsigned FULL = 0xffffffffu;
    const unsigned below = (1u << lane) - 1u;

    // stage s (float4 with |s|^2 in .w)
    for (int i = tid; i < NPE; i += GR_THREADS) {
        float a = g_s[(base + i) * 3 + 0];
        float b = g_s[(base + i) * 3 + 1];
        float c = g_s[(base + i) * 3 + 2];
        s4[i] = make_float4(a, b, c, dot3(a, b, c, a, b, c));
    }
    for (int i = tid; i < (int)(GR_WARPS * KMAX); i += GR_THREADS) cjall[i] = 0u;
    __syncthreads();

    unsigned* cj  = cjall + w * KMAX;
    unsigned* eqs = eqall + w * EQCAP;
    const float invk = 1.f / (float)k;
    const unsigned uk = (unsigned)k;

    for (int nn = 0; nn < NPW; ++nn) {
        const int i = sub * (GR_WARPS * NPW) + w * NPW + nn;
        const float4 si = s4[i];

        // ---- distances -> ordered uint keys, kept in registers ----
        unsigned key[64];
#pragma unroll
        for (int t = 0; t < 64; ++t) {
            int j = (t << 5) | lane;
            float4 sj = s4[j];
            float dd = (si.w + sj.w) - 2.f * dot3(si.x, si.y, si.z, sj.x, sj.y, sj.z);
            key[t] = f2u(dd);
        }

        // ---- common-prefix detection (skip bits where all 2048 keys agree) ----
        unsigned av = 0xffffffffu, ov = 0u;
#pragma unroll
        for (int t = 0; t < 64; ++t) { av &= key[t]; ov |= key[t]; }
        av = __reduce_and_sync(FULL, av);
        ov = __reduce_or_sync(FULL, ov);
        unsigned diff = av ^ ov;
        unsigned tau;
        if (diff == 0u) {
            tau = av;  // all keys identical
        } else {
            int hb = 31 - __clz(diff);
            unsigned mask = (hb == 31) ? 0xffffffffu : ((2u << hb) - 1u);
            unsigned p = av & ~mask;   // shared high bits
            for (int bit = hb; bit >= 0; --bit) {
                unsigned trial = p + (1u << bit);
                unsigned c = 0;
#pragma unroll
                for (int t = 0; t < 64; ++t) c += (key[t] < trial) ? 1u : 0u;
                c = __reduce_add_sync(FULL, c);
                if (c < uk) p = trial;   // k-th smallest >= trial -> bit is 1
            }
            tau = p;   // exact k-th smallest key
        }

        // ---- compaction: strict-less first, then rk smallest-index ties ----
        unsigned cnt = 0, ecnt = 0;
#pragma unroll
        for (int t = 0; t < 64; ++t) {
            int j = (t << 5) | lane;
            unsigned u = key[t];
            bool lt = u < tau;
            unsigned bl = __ballot_sync(FULL, lt);
            if (lt) {
                unsigned p = cnt + (unsigned)__popc(bl & below);
                if (p < KMAX) cj[p] = (unsigned)j;
            }
            cnt += __popc(bl);
            bool eqf = (u == tau);
            unsigned be = __ballot_sync(FULL, eqf);
            if (eqf) {
                unsigned p = ecnt + (unsigned)__popc(be & below);
                if (p < EQCAP) eqs[p] = (unsigned)j;
            }
            ecnt += __popc(be);
        }
        __syncwarp();
        unsigned rk = (uk > cnt) ? (uk - cnt) : 0u;   // ties to take
        if (ecnt > EQCAP) ecnt = EQCAP;
        for (unsigned m = lane; m < ecnt; m += 32) {
            unsigned j = eqs[m];
            unsigned r = 0;
            for (unsigned q = 0; q < ecnt; ++q) r += (eqs[q] < j);
            unsigned p = cnt + r;
            if (r < rk && p < KMAX) cj[p] = j;
        }
        __syncwarp();

        // ---- aggregate over the k selected neighbors ----
        // h read straight from L2 (per-event working set 96KB, resident)
        float sum[12], mx[12];
#pragma unroll
        for (int d = 0; d < 12; ++d) { sum[d] = 0.f; mx[d] = -FLT_MAX; }
        for (int m = lane; m < k; m += 32) {
            unsigned j = cj[m] & 2047u;   // masked: reads always in-bounds
            float4 sj = s4[j];
            float dd = (si.w + sj.w) - 2.f * dot3(si.x, si.y, si.z, sj.x, sj.y, sj.z);
            float wgt = __expf(-10.f * fmaxf(dd, 0.f));
            const float4* hp = (const float4*)&g_h[(size_t)(base + j) * 12];
            float4 ha = hp[0], hb = hp[1], hc = hp[2];
            float mv;
            mv = wgt * ha.x; sum[0] += mv; mx[0] = fmaxf(mx[0], mv);
            mv = wgt * ha.y; sum[1] += mv; mx[1] = fmaxf(mx[1], mv);
            mv = wgt * ha.z; sum[2] += mv; mx[2] = fmaxf(mx[2], mv);
            mv = wgt * ha.w; sum[3] += mv; mx[3] = fmaxf(mx[3], mv);
            mv = wgt * hb.x; sum[4] += mv; mx[4] = fmaxf(mx[4], mv);
            mv = wgt * hb.y; sum[5] += mv; mx[5] = fmaxf(mx[5], mv);
            mv = wgt * hb.z; sum[6] += mv; mx[6] = fmaxf(mx[6], mv);
            mv = wgt * hb.w; sum[7] += mv; mx[7] = fmaxf(mx[7], mv);
            mv = wgt * hc.x; sum[8] += mv; mx[8] = fmaxf(mx[8], mv);
            mv = wgt * hc.y; sum[9] += mv; mx[9] = fmaxf(mx[9], mv);
            mv = wgt * hc.z; sum[10] += mv; mx[10] = fmaxf(mx[10], mv);
            mv = wgt * hc.w; sum[11] += mv; mx[11] = fmaxf(mx[11], mv);
        }
#pragma unroll
        for (int d = 0; d < 12; ++d) {
            float v = sum[d], m = mx[d];
#pragma unroll
            for (int off = 16; off; off >>= 1) {
                v += __shfl_xor_sync(FULL, v, off);
                m = fmaxf(m, __shfl_xor_sync(FULL, m, off));
            }
            sum[d] = v; mx[d] = m;
        }
        if (lane == 0) {
            float4* o = (float4*)&g_agg[(size_t)(base + i) * 24];
            o[0] = make_float4(sum[0] * invk, sum[1] * invk, sum[2] * invk, sum[3] * invk);
            o[1] = make_float4(sum[4] * invk, sum[5] * invk, sum[6] * invk, sum[7] * invk);
            o[2] = make_float4(sum[8] * invk, sum[9] * invk, sum[10] * invk, sum[11] * invk);
            o[3] = make_float4(mx[0], mx[1], mx[2], mx[3]);
            o[4] = make_float4(mx[4], mx[5], mx[6], mx[7]);
            o[5] = make_float4(mx[8], mx[9], mx[10], mx[11]);
        }
        __syncwarp();
    }
}

// ---------------- K3: lin_out1 + lin_out2 + 2-layer post-MLP -> t ----------------
__global__ void k_post(const float* __restrict__ Wg1, const float* __restrict__ Wg2,
                       const float* __restrict__ bg2, const float* __restrict__ Wp1,
                       const float* __restrict__ bp1, const float* __restrict__ Wp2,
                       const float* __restrict__ bp2) {
    __shared__ float wg1[6 * 24], wg2[24 * 24], wp1[27 * 6], wp2[6 * 6];
    __shared__ float sb2[24], sp1[6], sp2[6];
    int tid = threadIdx.x;
    for (int i = tid; i < 144; i += blockDim.x) wg1[i] = Wg1[i];
    for (int i = tid; i < 576; i += blockDim.x) wg2[i] = Wg2[i];
    for (int i = tid; i < 162; i += blockDim.x) wp1[i] = Wp1[i];
    for (int i = tid; i < 36;  i += blockDim.x) wp2[i] = Wp2[i];
    for (int i = tid; i < 24;  i += blockDim.x) sb2[i] = bg2[i];
    for (int i = tid; i < 6;   i += blockDim.x) { sp1[i] = bp1[i]; sp2[i] = bp2[i]; }
    __syncthreads();

    int n = blockIdx.x * blockDim.x + tid;
    if (n >= NTOT) return;
    float xi[6], ag[24], sv[3];
#pragma unroll
    for (int d = 0; d < 6; ++d) xi[d] = g_x[n * 6 + d];
#pragma unroll
    for (int q = 0; q < 24; ++q) ag[q] = g_agg[n * 24 + q];
#pragma unroll
    for (int c = 0; c < 3; ++c) sv[c] = g_s[n * 3 + c];

    float o[24];
#pragma unroll
    for (int c = 0; c < 24; ++c) {
        float a = sb2[c];
#pragma unroll
        for (int d = 0; d < 6; ++d) a = fmaf(xi[d], wg1[d * 24 + c], a);
#pragma unroll
        for (int q = 0; q < 24; ++q) a = fmaf(ag[q], wg2[q * 24 + c], a);
        o[c] = a;
    }
    float t1[6];
#pragma unroll
    for (int d = 0; d < 6; ++d) {
        float a = sp1[d];
#pragma unroll
        for (int c = 0; c < 24; ++c) a = fmaf(o[c], wp1[c * 6 + d], a);
#pragma unroll
        for (int c = 0; c < 3; ++c) a = fmaf(sv[c], wp1[(24 + c) * 6 + d], a);
        t1[d] = eluf(a);
    }
#pragma unroll
    for (int d = 0; d < 6; ++d) {
        float a = sp2[d];
#pragma unroll
        for (int q = 0; q < 6; ++q) a = fmaf(t1[q], wp2[q * 6 + d], a);
        g_t[n * 6 + d] = eluf(a);
    }
}

// ---------------- K4: per-event mean/min/max of t ----------------
__global__ void k_red() {
    __shared__ float ssum[256 * 6], smn[256 * 6], smx[256 * 6];
    int e = blockIdx.x, tid = threadIdx.x;
    int base = e * NPE;
    float s6[6], mn6[6], mx6[6];
#pragma unroll
    for (int d = 0; d < 6; ++d) { s6[d] = 0.f; mn6[d] = FLT_MAX; mx6[d] = -FLT_MAX; }
    for (int i = tid; i < NPE; i += 256) {
#pragma unroll
        for (int d = 0; d < 6; ++d) {
            float v = g_t[(base + i) * 6 + d];
            s6[d] += v; mn6[d] = fminf(mn6[d], v); mx6[d] = fmaxf(mx6[d], v);
        }
    }
#pragma unroll
    for (int d = 0; d < 6; ++d) { ssum[tid * 6 + d] = s6[d]; smn[tid * 6 + d] = mn6[d]; smx[tid * 6 + d] = mx6[d]; }
    __syncthreads();
    for (int s = 128; s > 0; s >>= 1) {
        if (tid < s) {
#pragma unroll
            for (int d = 0; d < 6; ++d) {
                ssum[tid * 6 + d] += ssum[(tid + s) * 6 + d];
                smn[tid * 6 + d] = fminf(smn[tid * 6 + d], smn[(tid + s) * 6 + d]);
                smx[tid * 6 + d] = fmaxf(smx[tid * 6 + d], smx[(tid + s) * 6 + d]);
            }
        }
        __syncthreads();
    }
    if (tid == 0) {
#pragma unroll
        for (int d = 0; d < 6; ++d) {
            g_stats[e * 18 + d]      = ssum[d] * (1.f / (float)NPE);
            g_stats[e * 18 + 6 + d]  = smn[d];
            g_stats[e * 18 + 12 + d] = smx[d];
        }
    }
}

// ---------------- K5: global-exchange dense + elu -> new x (+ next-layer proj) ----------------
__global__ void k_ex(int layer, int do_proj,
                     const float* __restrict__ Wex, const float* __restrict__ bex,
                     const float* __restrict__ Ws, const float* __restrict__ bs,
                     const float* __restrict__ Wh, const float* __restrict__ bh) {
    int n = blockIdx.x * blockDim.x + threadIdx.x;
    if (n >= NTOT) return;
    int e = n >> 11;
    float ex[24];
#pragma unroll
    for (int c = 0; c < 18; ++c) ex[c] = g_stats[e * 18 + c];
#pragma unroll
    for (int d = 0; d < 6; ++d) ex[18 + d] = g_t[n * 6 + d];
    float xv[6];
#pragma unroll
    for (int d = 0; d < 6; ++d) {
        float a = bex[d];
#pragma unroll
        for (int c = 0; c < 24; ++c) a = fmaf(ex[c], Wex[c * 6 + d], a);
        float v = eluf(a);
        xv[d] = v;
        g_x[n * 6 + d] = v;
        g_feats[n * 24 + layer * 6 + d] = v;
    }
    if (do_proj) {
#pragma unroll
        for (int sp = 0; sp < 3; ++sp) {
            float a = bs[sp];
#pragma unroll
            for (int d = 0; d < 6; ++d) a = fmaf(xv[d], Ws[d * 3 + sp], a);
            g_s[n * 3 + sp] = a;
        }
#pragma unroll
        for (int p = 0; p < 12; ++p) {
            float a = bh[p];
#pragma unroll
            for (int d = 0; d < 6; ++d) a = fmaf(xv[d], Wh[d * 12 + p], a);
            g_h[n * 12 + p] = a;
        }
    }
}

// ---------------- K6: output head ----------------
#define H_WD0 0
#define H_BD0 144
#define H_WD  150
#define H_BD  258
#define H_WH1 276
#define H_BH1 660
#define H_WH2 724
#define H_BH2 4820
#define H_WH3 4884
#define H_BH3 8980
#define H_WC  9044
#define H_BC  10964
#define H_WB  10994
#define H_BB  11058
#define H_TOT 11059

__global__ void __launch_bounds__(128) k_head(
    const float* __restrict__ Wd0, const float* __restrict__ bd0,
    const float* __restrict__ Wd,  const float* __restrict__ bd,
    const float* __restrict__ Wh1, const float* __restrict__ bh1,
    const float* __restrict__ Wh2, const float* __restrict__ bh2,
    const float* __restrict__ Wh3, const float* __restrict__ bh3,
    const float* __restrict__ Wc,  const float* __restrict__ bc,
    const float* __restrict__ Wb,  const float* __restrict__ bb,
    float* __restrict__ out) {
    __shared__ float S[H_TOT];
    int tid = threadIdx.x;
    for (int i = tid; i < 144;  i += 128) S[H_WD0 + i] = Wd0[i];
    for (int i = tid; i < 6;    i += 128) S[H_BD0 + i] = bd0[i];
    for (int i = tid; i < 108;  i += 128) S[H_WD + i]  = Wd[i];
    for (int i = tid; i < 18;   i += 128) S[H_BD + i]  = bd[i];
    for (int i = tid; i < 384;  i += 128) S[H_WH1 + i] = Wh1[i];
    for (int i = tid; i < 64;   i += 128) S[H_BH1 + i] = bh1[i];
    for (int i = tid; i < 4096; i += 128) S[H_WH2 + i] = Wh2[i];
    for (int i = tid; i < 64;   i += 128) S[H_BH2 + i] = bh2[i];
    for (int i = tid; i < 4096; i += 128) S[H_WH3 + i] = Wh3[i];
    for (int i = tid; i < 64;   i += 128) S[H_BH3 + i] = bh3[i];
    for (int i = tid; i < 1920; i += 128) S[H_WC + i]  = Wc[i];
    for (int i = tid; i < 30;   i += 128) S[H_BC + i]  = bc[i];
    for (int i = tid; i < 64;   i += 128) S[H_WB + i]  = Wb[i];
    for (int i = tid; i < 1;    i += 128) S[H_BB + i]  = bb[i];
    __syncthreads();

    int n = blockIdx.x * 128 + tid;
    if (n >= NTOT) return;

    float f24[24];
#pragma unroll
    for (int c = 0; c < 24; ++c) f24[c] = g_feats[n * 24 + c];

    float y6[6];
#pragma unroll
    for (int d = 0; d < 6; ++d) {
        float a = S[H_BD0 + d];
#pragma unroll
        for (int c = 0; c < 24; ++c) a = fmaf(f24[c], S[H_WD0 + c * 6 + d], a);
        y6[d] = eluf(a);
    }
    for (int j = 0; j < 3; ++j) {
        float z6[6];
#pragma unroll
        for (int d = 0; d < 6; ++d) {
            float a = S[H_BD + j * 6 + d];
#pragma unroll
            for (int c = 0; c < 6; ++c) a = fmaf(y6[c], S[H_WD + j * 36 + c * 6 + d], a);
            z6[d] = eluf(a);
        }
#pragma unroll
        for (int d = 0; d < 6; ++d) y6[d] = z6[d];
    }

    float ya[64];
#pragma unroll
    for (int d = 0; d < 64; ++d) ya[d] = S[H_BH1 + d];
    for (int c = 0; c < 6; ++c) {
        float v = y6[c];
#pragma unroll
        for (int d = 0; d < 64; ++d) ya[d] = fmaf(v, S[H_WH1 + c * 64 + d], ya[d]);
    }
#pragma unroll
    for (int d = 0; d < 64; ++d) ya[d] = eluf(ya[d]);

    float yc[64];
#pragma unroll
    for (int d = 0; d < 64; ++d) yc[d] = S[H_BH3 + d];
    for (int c = 0; c < 64; ++c) {
        float a = S[H_BH2 + c];
#pragma unroll
        for (int q = 0; q < 64; ++q) a = fmaf(ya[q], S[H_WH2 + q * 64 + c], a);
        a = eluf(a);
#pragma unroll
        for (int d = 0; d < 64; ++d) yc[d] = fmaf(a, S[H_WH3 + c * 64 + d], yc[d]);
    }

    float o[30];
#pragma unroll
    for (int c = 0; c < 30; ++c) o[c] = S[H_BC + c];
    float ob = S[H_BB];
    for (int q = 0; q < 64; ++q) {
        float v = yc[q];
#pragma unroll
        for (int c = 0; c < 30; ++c) o[c] = fmaf(v, S[H_WC + q * 30 + c], o[c]);
        ob = fmaf(v, S[H_WB + q], ob);
    }
#pragma unroll
    for (int c = 0; c < 30; ++c) out[n * 31 + c] = o[c];
    out[n * 31 + 30] = ob;
}

// ---------------- launch ----------------
extern "C" void kernel_launch(void* const* d_in, const int* in_sizes, int n_in,
                              void* d_out, int out_size) {
    const float* X    = (const float*)d_in[0];
    const float* Win  = (const float*)d_in[1];
    const float* Ws   = (const float*)d_in[2];
    const float* bs   = (const float*)d_in[3];
    const float* Wh   = (const float*)d_in[4];
    const float* bh   = (const float*)d_in[5];
    const float* Wg1  = (const float*)d_in[6];
    const float* Wg2  = (const float*)d_in[7];
    const float* bg2  = (const float*)d_in[8];
    const float* Wp1  = (const float*)d_in[9];
    const float* bp1  = (const float*)d_in[10];
    const float* Wp2  = (const float*)d_in[11];
    const float* bp2  = (const float*)d_in[12];
    const float* Wex  = (const float*)d_in[13];
    const float* bex  = (const float*)d_in[14];
    const float* Wd0  = (const float*)d_in[15];
    const float* bd0  = (const float*)d_in[16];
    const float* Wd   = (const float*)d_in[17];
    const float* bd   = (const float*)d_in[18];
    const float* Wh1  = (const float*)d_in[19];
    const float* bh1  = (const float*)d_in[20];
    const float* Wh2  = (const float*)d_in[21];
    const float* bh2  = (const float*)d_in[22];
    const float* Wh3  = (const float*)d_in[23];
    const float* bh3  = (const float*)d_in[24];
    const float* Wc   = (const float*)d_in[25];
    const float* bc   = (const float*)d_in[26];
    const float* Wb   = (const float*)d_in[27];
    const float* bb   = (const float*)d_in[28];

    cudaFuncSetAttribute(k_grav, cudaFuncAttributeMaxDynamicSharedMemorySize,
                         (int)GRAV_SMEM_BYTES);

    const int KS[4] = {16, 128, 16, 256};
    const int GRAV_BLOCKS_X = NPE / (GR_WARPS * NPW);   // 64

    k_embed<<<NTOT / 256, 256>>>(X, Win, Ws, bs, Wh, bh);
    for (int i = 0; i < 4; ++i) {
        k_grav<<<dim3(GRAV_BLOCKS_X, NB), GR_THREADS, GRAV_SMEM_BYTES>>>(KS[i]);
        k_post<<<NTOT / 256, 256>>>(Wg1 + i * 144, Wg2 + i * 576, bg2 + i * 24,
                                    Wp1 + i * 162, bp1 + i * 6, Wp2 + i * 36, bp2 + i * 6);
        k_red<<<NB, 256>>>();
        int nx = (i + 1) & 3;      // valid offsets even when do_proj==0
        k_ex<<<NTOT / 256, 256>>>(i, (i < 3) ? 1 : 0, Wex + i * 144, bex + i * 6,
                                  Ws + nx * 18, bs + nx * 3, Wh + nx * 72, bh + nx * 12);
    }
    k_head<<<NTOT / 128, 128>>>(Wd0, bd0, Wd, bd, Wh1, bh1, Wh2, bh2, Wh3, bh3,
                                Wc, bc, Wb, bb, (float*)d_out);
}